// round 9
// baseline (speedup 1.0000x reference)
#include <cuda_runtime.h>
#include <cuda_bf16.h>
#include <cstdint>

#define C 256
#define MAXN 100000
#define MAXE 3200000
#define KTOT 512
#define NCH  8192   // scan chunks

// Scratch (__device__ globals; allocation-free rule)
__device__ __align__(256) __nv_bfloat16 g_axH[(size_t)MAXN * C];
__device__ __align__(256) __nv_bfloat16 g_axL[(size_t)MAXN * C];
__device__ __align__(256) __nv_bfloat16 g_h0H[(size_t)MAXN * C];
__device__ __align__(256) __nv_bfloat16 g_h0L[(size_t)MAXN * C];
__device__ __align__(256) __nv_bfloat16 g_MtH[C * KTOT];   // M^T hi, [n][k]
__device__ __align__(256) __nv_bfloat16 g_MtL[C * KTOT];   // M^T lo, [n][k]
__device__ int   g_is64;
__device__ int   g_cnt[MAXN];
__device__ int   g_rowstart[MAXN + 1];
__device__ int   g_cursor[MAXN];
__device__ __align__(16) uint2 g_colval[MAXE];             // interleaved CSR
__device__ int   g_psum[NCH];
__device__ int   g_poff[NCH];

// ---------------------------------------------------------------------------
__device__ __forceinline__ void split_pair(float x, float y,
                                           uint32_t& hi, uint32_t& lo) {
    __nv_bfloat162 h = __floats2bfloat162_rn(x, y);
    float hx = __bfloat162float(__low2bfloat16(h));
    float hy = __bfloat162float(__high2bfloat16(h));
    __nv_bfloat162 l = __floats2bfloat162_rn(x - hx, y - hy);
    hi = *reinterpret_cast<uint32_t*>(&h);
    lo = *reinterpret_cast<uint32_t*>(&l);
}

// ---------------------------------------------------------------------------
__global__ void detect_idx_kernel(const int* __restrict__ ei32, int nwords) {
    if (threadIdx.x != 0 || blockIdx.x != 0) return;
    int nonzero_odd = 0;
    int lim = nwords < 1024 ? nwords : 1024;
    for (int i = 1; i < lim; i += 2) nonzero_odd += (ei32[i] != 0);
    g_is64 = (nonzero_odd == 0) ? 1 : 0;
}

__global__ void zero_cnt_kernel(int N) {
    int i = blockIdx.x * blockDim.x + threadIdx.x;
    if (i < N) g_cnt[i] = 0;
}

// Build transposed+split blend matrix g_Mt[n][k]
__global__ void build_Mt_kernel(const float* __restrict__ W1,
                                const float* __restrict__ W2,
                                const float* __restrict__ p_alpha,
                                const float* __restrict__ p_beta) {
    float a = *p_alpha, b = *p_beta;
    float c1 = (1.f - a) * (1.f - b);
    float c2 = (1.f - a) * b;
    float c3 = a * (1.f - b);
    float c4 = a * b;
    int i = blockIdx.x * blockDim.x + threadIdx.x;
    if (i >= C * KTOT) return;
    int n = i / KTOT, k = i % KTOT;
    float v;
    if (k < C) {
        v = c2 * W1[k * C + n] + (k == n ? c1 : 0.f);
    } else {
        int k2 = k - C;
        v = c4 * W2[k2 * C + n] + (k2 == n ? c3 : 0.f);
    }
    __nv_bfloat16 hi = __float2bfloat16_rn(v);
    g_MtH[i] = hi;
    g_MtL[i] = __float2bfloat16_rn(v - __bfloat162float(hi));
}

// Pre-split h0 into bf16 hi/lo
__global__ void split_h0_kernel(const float* __restrict__ h0, int total4) {
    int i = blockIdx.x * blockDim.x + threadIdx.x;
    if (i >= total4) return;
    float4 v = __ldg(&reinterpret_cast<const float4*>(h0)[i]);
    uint32_t h0w, l0w, h1w, l1w;
    split_pair(v.x, v.y, h0w, l0w);
    split_pair(v.z, v.w, h1w, l1w);
    reinterpret_cast<uint2*>(g_h0H)[i] = make_uint2(h0w, h1w);
    reinterpret_cast<uint2*>(g_h0L)[i] = make_uint2(l0w, l1w);
}

// ---------------------------------------------------------------------------
// CSR build: histogram (4-wide) -> 3-phase scan -> ticket scatter
// ---------------------------------------------------------------------------
__global__ void hist_kernel(const void* __restrict__ ei_raw, int E, int N) {
    const int is64 = g_is64;
    const long long* ei64 = (const long long*)ei_raw;
    const int*       ei32 = (const int*)ei_raw;
    int base   = (blockIdx.x * blockDim.x + threadIdx.x) * 4;
    int stride = gridDim.x * blockDim.x * 4;
    for (int e = base; e + 4 <= E; e += stride) {
        int r0, r1, r2, r3;
        if (is64) {
            longlong2 p0 = __ldg(reinterpret_cast<const longlong2*>(&ei64[e]));
            longlong2 p1 = __ldg(reinterpret_cast<const longlong2*>(&ei64[e + 2]));
            r0 = (int)p0.x; r1 = (int)p0.y; r2 = (int)p1.x; r3 = (int)p1.y;
        } else {
            int4 p = __ldg(reinterpret_cast<const int4*>(&ei32[e]));
            r0 = p.x; r1 = p.y; r2 = p.z; r3 = p.w;
        }
        if ((unsigned)r0 < (unsigned)N) atomicAdd(&g_cnt[r0], 1);
        if ((unsigned)r1 < (unsigned)N) atomicAdd(&g_cnt[r1], 1);
        if ((unsigned)r2 < (unsigned)N) atomicAdd(&g_cnt[r2], 1);
        if ((unsigned)r3 < (unsigned)N) atomicAdd(&g_cnt[r3], 1);
    }
    if (base == 0) {
        for (int e = E & ~3; e < E; e++) {
            int r = is64 ? (int)__ldg(&ei64[e]) : __ldg(&ei32[e]);
            if ((unsigned)r < (unsigned)N) atomicAdd(&g_cnt[r], 1);
        }
    }
}

__global__ void scan_p1(int N) {
    int j = blockIdx.x * blockDim.x + threadIdx.x;
    if (j >= NCH) return;
    int ch = (N + NCH - 1) / NCH;
    int s = j * ch, e = min(s + ch, N);
    int acc = 0;
    for (int i = s; i < e; i++) acc += g_cnt[i];
    g_psum[j] = acc;
}

__global__ void scan_p2() {
    __shared__ int sh[1024];
    int t = threadIdx.x;
    int loc[8];
    int s = 0;
    #pragma unroll
    for (int k = 0; k < 8; k++) { loc[k] = g_psum[t * 8 + k]; s += loc[k]; }
    sh[t] = s;
    __syncthreads();
    for (int off = 1; off < 1024; off <<= 1) {
        int add = (t >= off) ? sh[t - off] : 0;
        __syncthreads();
        sh[t] += add;
        __syncthreads();
    }
    int run = sh[t] - s;
    #pragma unroll
    for (int k = 0; k < 8; k++) { g_poff[t * 8 + k] = run; run += loc[k]; }
}

__global__ void scan_p3(int N, int E) {
    int j = blockIdx.x * blockDim.x + threadIdx.x;
    if (j >= NCH) return;
    int ch = (N + NCH - 1) / NCH;
    int s = j * ch, e = min(s + ch, N);
    int base = g_poff[j];
    for (int i = s; i < e; i++) {
        int c = g_cnt[i];
        g_rowstart[i] = base;
        g_cursor[i]   = base;
        base += c;
    }
    if (j == 0) g_rowstart[N] = E;
}

__global__ void scatter_kernel(const void* __restrict__ ei_raw,
                               const float* __restrict__ vals, int E, int N) {
    const int is64 = g_is64;
    const long long* ei64 = (const long long*)ei_raw;
    const int*       ei32 = (const int*)ei_raw;
    for (int e = blockIdx.x * blockDim.x + threadIdx.x; e < E;
         e += gridDim.x * blockDim.x) {
        int row, col;
        if (is64) {
            row = (int)__ldg(&ei64[e]);
            col = (int)__ldg(&ei64[(size_t)E + e]);
        } else {
            row = __ldg(&ei32[e]);
            col = __ldg(&ei32[(size_t)E + e]);
        }
        if ((unsigned)row >= (unsigned)N || (unsigned)col >= (unsigned)N) continue;
        int pos = atomicAdd(&g_cursor[row], 1);
        __stcs(&g_colval[pos],
               make_uint2((unsigned)col, __float_as_uint(__ldg(&vals[e]))));
    }
}

// ---------------------------------------------------------------------------
// SpMM over CSR: one warp per row; streaming colval loads; bf16 hi/lo stores.
// ---------------------------------------------------------------------------
__global__ __launch_bounds__(256)
void spmm_csr_kernel(const float* __restrict__ x, int N) {
    int warp = (blockIdx.x * blockDim.x + threadIdx.x) >> 5;
    int lane = threadIdx.x & 31;
    int nw   = (gridDim.x * blockDim.x) >> 5;
    for (int r = warp; r < N; r += nw) {
        int s = g_rowstart[r];
        int e = g_rowstart[r + 1];
        float4 acc0 = make_float4(0.f, 0.f, 0.f, 0.f);
        float4 acc1 = make_float4(0.f, 0.f, 0.f, 0.f);
        int i = s;
        for (; i + 2 <= e; i += 2) {
            uint2 cv0 = __ldcs(&g_colval[i]);
            uint2 cv1 = __ldcs(&g_colval[i + 1]);
            float v0 = __uint_as_float(cv0.y);
            float v1 = __uint_as_float(cv1.y);
            const float4* x0 = reinterpret_cast<const float4*>(x + (size_t)cv0.x * C);
            const float4* x1 = reinterpret_cast<const float4*>(x + (size_t)cv1.x * C);
            float4 a0 = __ldg(&x0[lane]),      b0 = __ldg(&x0[lane + 32]);
            float4 a1 = __ldg(&x1[lane]),      b1 = __ldg(&x1[lane + 32]);
            acc0.x += v0 * a0.x + v1 * a1.x;
            acc0.y += v0 * a0.y + v1 * a1.y;
            acc0.z += v0 * a0.z + v1 * a1.z;
            acc0.w += v0 * a0.w + v1 * a1.w;
            acc1.x += v0 * b0.x + v1 * b1.x;
            acc1.y += v0 * b0.y + v1 * b1.y;
            acc1.z += v0 * b0.z + v1 * b1.z;
            acc1.w += v0 * b0.w + v1 * b1.w;
        }
        if (i < e) {
            uint2 cv0 = __ldcs(&g_colval[i]);
            float v0 = __uint_as_float(cv0.y);
            const float4* x0 = reinterpret_cast<const float4*>(x + (size_t)cv0.x * C);
            float4 a0 = __ldg(&x0[lane]);
            float4 b0 = __ldg(&x0[lane + 32]);
            acc0.x += v0 * a0.x; acc0.y += v0 * a0.y;
            acc0.z += v0 * a0.z; acc0.w += v0 * a0.w;
            acc1.x += v0 * b0.x; acc1.y += v0 * b0.y;
            acc1.z += v0 * b0.z; acc1.w += v0 * b0.w;
        }
        uint32_t h0w, l0w, h1w, l1w;
        split_pair(acc0.x, acc0.y, h0w, l0w);
        split_pair(acc0.z, acc0.w, h1w, l1w);
        uint2* dH = reinterpret_cast<uint2*>(g_axH + (size_t)r * C + lane * 4);
        uint2* dL = reinterpret_cast<uint2*>(g_axL + (size_t)r * C + lane * 4);
        __stcs(dH, make_uint2(h0w, h1w));
        __stcs(dL, make_uint2(l0w, l1w));
        split_pair(acc1.x, acc1.y, h0w, l0w);
        split_pair(acc1.z, acc1.w, h1w, l1w);
        dH = reinterpret_cast<uint2*>(g_axH + (size_t)r * C + 128 + lane * 4);
        dL = reinterpret_cast<uint2*>(g_axL + (size_t)r * C + 128 + lane * 4);
        __stcs(dH, make_uint2(h0w, h1w));
        __stcs(dL, make_uint2(l0w, l1w));
    }
}

// ---------------------------------------------------------------------------
// Tensor-core half-GEMM: out[N,256] (+)= A[N,256] @ M[mtk..mtk+256, :]
// use_h0 selects the A source from device globals (NOT host pointers — a
// __device__ symbol referenced from host code is invalid; that was the R8 bug).
// accum=0: out = result (h0 half); accum=1: out += result (ax half).
// ---------------------------------------------------------------------------
#define BM 128
#define BN 128
#define BK 32
#define KHALF 256
#define LDS_W 20                     // words/row: 16 data + 4 pad
#define ARR_W (128 * LDS_W)          // 2560 words per array
#define STG_W (4 * ARR_W)            // words per stage
#define SMEM_BYTES (2 * STG_W * 4)   // 81920

__device__ __forceinline__ uint32_t s2u(const void* p) {
    uint32_t a;
    asm("{ .reg .u64 t; cvta.to.shared.u64 t, %1; cvt.u32.u64 %0, t; }"
        : "=r"(a) : "l"(p));
    return a;
}
__device__ __forceinline__ void cp16(uint32_t daddr, const void* g) {
    asm volatile("cp.async.cg.shared.global [%0], [%1], 16;"
                 :: "r"(daddr), "l"(g));
}
__device__ __forceinline__ void cp16z(uint32_t daddr, const void* g) {
    asm volatile("cp.async.cg.shared.global [%0], [%1], 16, 0;"
                 :: "r"(daddr), "l"(g));
}
__device__ __forceinline__ void cp_commit() {
    asm volatile("cp.async.commit_group;");
}
__device__ __forceinline__ void cp_wait0() {
    asm volatile("cp.async.wait_group 0;");
}
__device__ __forceinline__ void ldm_x4(uint32_t* r, uint32_t addr) {
    asm volatile("ldmatrix.sync.aligned.m8n8.x4.shared.b16 {%0,%1,%2,%3}, [%4];"
                 : "=r"(r[0]), "=r"(r[1]), "=r"(r[2]), "=r"(r[3]) : "r"(addr));
}
__device__ __forceinline__ void mma_bf16(float* c, const uint32_t* a,
                                         uint32_t b0, uint32_t b1) {
    asm volatile(
        "mma.sync.aligned.m16n8k16.row.col.f32.bf16.bf16.f32 "
        "{%0,%1,%2,%3}, {%4,%5,%6,%7}, {%8,%9}, {%0,%1,%2,%3};"
        : "+f"(c[0]), "+f"(c[1]), "+f"(c[2]), "+f"(c[3])
        : "r"(a[0]), "r"(a[1]), "r"(a[2]), "r"(a[3]), "r"(b0), "r"(b1));
}

__global__ __launch_bounds__(256, 2)
void gemm_half_kernel(int use_h0, int mtk, int accum,
                      float* __restrict__ out, int N) {
    extern __shared__ uint32_t smem[];
    const uint32_t sbase = s2u(smem);

    // resolve A source in DEVICE code
    const __nv_bfloat16* __restrict__ AH = use_h0 ? g_h0H : g_axH;
    const __nv_bfloat16* __restrict__ AL = use_h0 ? g_h0L : g_axL;

    const int tid  = threadIdx.x;
    const int lane = tid & 31;
    const int wid  = tid >> 5;
    const int warp_m = (wid & 3) * 32;
    const int warp_n = (wid >> 2) * 64;
    const int bn = blockIdx.x * BN;
    const int bm = blockIdx.y * BM;

    const int a_row = (lane & 7) + ((lane >> 3) & 1) * 8;
    const int a_k   = (lane >> 4) * 8;
    const int b_row = (lane & 7) + (lane >> 4) * 8;
    const int b_k   = ((lane >> 3) & 1) * 8;

    float acc[2][8][4];
    #pragma unroll
    for (int i = 0; i < 2; i++)
        #pragma unroll
        for (int j = 0; j < 8; j++)
            #pragma unroll
            for (int q = 0; q < 4; q++) acc[i][j][q] = 0.f;

    const int lrow = tid >> 1;
    const int lh   = tid & 1;
    const int arow = bm + lrow;
    const bool avalid = (arow < N);
    const int acl = avalid ? arow : 0;

    const int T = KHALF / BK;   // 8 tiles

    auto load_tile = [&](int t, int stg) {
        const int kt = t * BK;
        const size_t aoff = (size_t)acl * C + kt + lh * 16;
        const __nv_bfloat16* gAH = AH + aoff;
        const __nv_bfloat16* gAL = AL + aoff;
        const size_t boff = (size_t)(bn + lrow) * KTOT + mtk + kt + lh * 16;
        const __nv_bfloat16* gBH = g_MtH + boff;
        const __nv_bfloat16* gBL = g_MtL + boff;
        uint32_t drow = sbase + (stg * STG_W + lrow * LDS_W + lh * 8) * 4;
        #pragma unroll
        for (int c = 0; c < 2; c++) {
            if (avalid) {
                cp16(drow + c * 16,               gAH + c * 8);
                cp16(drow + ARR_W * 4 + c * 16,   gAL + c * 8);
            } else {
                cp16z(drow + c * 16,              gAH + c * 8);
                cp16z(drow + ARR_W * 4 + c * 16,  gAL + c * 8);
            }
            cp16(drow + 2 * ARR_W * 4 + c * 16,   gBH + c * 8);
            cp16(drow + 3 * ARR_W * 4 + c * 16,   gBL + c * 8);
        }
        cp_commit();
    };

    load_tile(0, 0);

    for (int t = 0; t < T; t++) {
        cp_wait0();
        __syncthreads();
        if (t + 1 < T) load_tile(t + 1, (t + 1) & 1);

        const int stg = t & 1;
        const uint32_t aH0 = sbase + (stg * STG_W) * 4;
        const uint32_t aL0 = aH0 + ARR_W * 4;
        const uint32_t bH0 = aH0 + 2 * ARR_W * 4;
        const uint32_t bL0 = aH0 + 3 * ARR_W * 4;

        #pragma unroll
        for (int ks = 0; ks < 2; ks++) {
            const int kk = ks * 16;
            uint32_t aH[2][4], aL[2][4];
            #pragma unroll
            for (int mt = 0; mt < 2; mt++) {
                uint32_t off = ((warp_m + mt * 16 + a_row) * LDS_W) * 4
                             + (kk + a_k) * 2;
                ldm_x4(aH[mt], aH0 + off);
                ldm_x4(aL[mt], aL0 + off);
            }
            #pragma unroll
            for (int ntp = 0; ntp < 4; ntp++) {
                uint32_t bH[4], bL[4];
                uint32_t off = ((warp_n + ntp * 16 + b_row) * LDS_W) * 4
                             + (kk + b_k) * 2;
                ldm_x4(bH, bH0 + off);
                ldm_x4(bL, bL0 + off);
                #pragma unroll
                for (int mt = 0; mt < 2; mt++) {
                    #pragma unroll
                    for (int j = 0; j < 2; j++) {
                        float* c = acc[mt][ntp * 2 + j];
                        mma_bf16(c, aH[mt], bH[2*j], bH[2*j+1]);
                        mma_bf16(c, aH[mt], bL[2*j], bL[2*j+1]);
                        mma_bf16(c, aL[mt], bH[2*j], bH[2*j+1]);
                    }
                }
            }
        }
        __syncthreads();
    }

    #pragma unroll
    for (int mt = 0; mt < 2; mt++) {
        #pragma unroll
        for (int nt = 0; nt < 8; nt++) {
            int r0  = bm + warp_m + mt * 16 + (lane >> 2);
            int col = bn + warp_n + nt * 8 + (lane & 3) * 2;
            if (r0 < N) {
                float2* p = reinterpret_cast<float2*>(out + (size_t)r0 * C + col);
                float2 v = make_float2(acc[mt][nt][0], acc[mt][nt][1]);
                if (accum) { float2 o = *p; v.x += o.x; v.y += o.y; }
                *p = v;
            }
            int r1 = r0 + 8;
            if (r1 < N) {
                float2* p = reinterpret_cast<float2*>(out + (size_t)r1 * C + col);
                float2 v = make_float2(acc[mt][nt][2], acc[mt][nt][3]);
                if (accum) { float2 o = *p; v.x += o.x; v.y += o.y; }
                *p = v;
            }
        }
    }
}

// ---------------------------------------------------------------------------
// Launch: fork h0-half GEMM (tensor-bound) alongside CSR+SpMM (memory-bound).
// ---------------------------------------------------------------------------
extern "C" void kernel_launch(void* const* d_in, const int* in_sizes, int n_in,
                              void* d_out, int out_size) {
    const float* x    = (const float*)d_in[0];
    const float* vals = (const float*)d_in[1];
    const void*  ei   = d_in[2];
    const float* h0   = (const float*)d_in[3];
    const float* W1   = (const float*)d_in[4];
    const float* W2   = (const float*)d_in[5];
    const float* pa   = (const float*)d_in[6];
    const float* pb   = (const float*)d_in[7];
    float* out = (float*)d_out;

    const int N = in_sizes[0] / C;     // 100000
    int E = in_sizes[1];               // 3200000
    if (E > MAXE) E = MAXE;

    static cudaStream_t s2 = nullptr;
    static cudaEvent_t evA = nullptr, evB = nullptr;
    if (s2 == nullptr) {
        cudaStreamCreateWithFlags(&s2, cudaStreamNonBlocking);
        cudaEventCreateWithFlags(&evA, cudaEventDisableTiming);
        cudaEventCreateWithFlags(&evB, cudaEventDisableTiming);
        cudaFuncSetAttribute(gemm_half_kernel,
                             cudaFuncAttributeMaxDynamicSharedMemorySize,
                             SMEM_BYTES);
    }

    // main: prerequisites for h0-half GEMM
    detect_idx_kernel<<<1, 32>>>((const int*)ei, in_sizes[2]);
    build_Mt_kernel<<<(C * KTOT + 255) / 256, 256>>>(W1, W2, pa, pb);
    int total4 = N * C / 4;
    split_h0_kernel<<<(total4 + 255) / 256, 256>>>(h0, total4);
    cudaEventRecord(evA, 0);

    // side stream: right-term GEMM (tensor-bound), overlaps CSR+SpMM
    cudaStreamWaitEvent(s2, evA, 0);
    dim3 ggrid(C / BN, (N + BM - 1) / BM);
    gemm_half_kernel<<<ggrid, 256, SMEM_BYTES, s2>>>(1, C, 0, out, N);
    cudaEventRecord(evB, s2);

    // main: CSR build + SpMM (memory-bound)
    zero_cnt_kernel<<<(N + 255) / 256, 256>>>(N);
    hist_kernel<<<3125, 256>>>(ei, E, N);
    scan_p1<<<NCH / 256, 256>>>(N);
    scan_p2<<<1, 1024>>>();
    scan_p3<<<NCH / 256, 256>>>(N, E);
    scatter_kernel<<<4096, 256>>>(ei, vals, E, N);

    int spmm_blocks = (N * 32 + 255) / 256;
    spmm_csr_kernel<<<spmm_blocks, 256>>>(x, N);

    // join, then left-term GEMM accumulates into out
    cudaStreamWaitEvent(0, evB, 0);
    gemm_half_kernel<<<ggrid, 256, SMEM_BYTES>>>(0, 0, 1, out, N);
}

// round 10
// speedup vs baseline: 1.0630x; 1.0630x over previous
#include <cuda_runtime.h>
#include <cuda_bf16.h>
#include <cstdint>

#define C 256
#define MAXN 100000
#define MAXE 3200000
#define KTOT 512
#define NCH  8192   // scan chunks

// Scratch (__device__ globals; allocation-free rule)
__device__ __align__(256) __nv_bfloat16 g_axH[(size_t)MAXN * C];
__device__ __align__(256) __nv_bfloat16 g_axL[(size_t)MAXN * C];
__device__ __align__(256) __nv_bfloat16 g_h0H[(size_t)MAXN * C];
__device__ __align__(256) __nv_bfloat16 g_h0L[(size_t)MAXN * C];
__device__ __align__(256) __nv_bfloat16 g_MtH[C * KTOT];   // M^T hi, [n][k]
__device__ __align__(256) __nv_bfloat16 g_MtL[C * KTOT];   // M^T lo, [n][k]
__device__ int   g_is64;
__device__ int   g_cnt[MAXN];
__device__ int   g_rowstart[MAXN + 1];
__device__ int   g_cursor[MAXN];
__device__ __align__(16) uint2 g_colval[MAXE];             // interleaved CSR
__device__ int   g_psum[NCH];
__device__ int   g_poff[NCH];

// ---------------------------------------------------------------------------
__device__ __forceinline__ void split_pair(float x, float y,
                                           uint32_t& hi, uint32_t& lo) {
    __nv_bfloat162 h = __floats2bfloat162_rn(x, y);
    float hx = __bfloat162float(__low2bfloat16(h));
    float hy = __bfloat162float(__high2bfloat16(h));
    __nv_bfloat162 l = __floats2bfloat162_rn(x - hx, y - hy);
    hi = *reinterpret_cast<uint32_t*>(&h);
    lo = *reinterpret_cast<uint32_t*>(&l);
}

// ---------------------------------------------------------------------------
__global__ void detect_idx_kernel(const int* __restrict__ ei32, int nwords) {
    if (threadIdx.x != 0 || blockIdx.x != 0) return;
    int nonzero_odd = 0;
    int lim = nwords < 1024 ? nwords : 1024;
    for (int i = 1; i < lim; i += 2) nonzero_odd += (ei32[i] != 0);
    g_is64 = (nonzero_odd == 0) ? 1 : 0;
}

__global__ void zero_cnt_kernel(int N) {
    int i = blockIdx.x * blockDim.x + threadIdx.x;
    if (i < N) g_cnt[i] = 0;
}

// Build transposed+split blend matrix g_Mt[n][k]
__global__ void build_Mt_kernel(const float* __restrict__ W1,
                                const float* __restrict__ W2,
                                const float* __restrict__ p_alpha,
                                const float* __restrict__ p_beta) {
    float a = *p_alpha, b = *p_beta;
    float c1 = (1.f - a) * (1.f - b);
    float c2 = (1.f - a) * b;
    float c3 = a * (1.f - b);
    float c4 = a * b;
    int i = blockIdx.x * blockDim.x + threadIdx.x;
    if (i >= C * KTOT) return;
    int n = i / KTOT, k = i % KTOT;
    float v;
    if (k < C) {
        v = c2 * W1[k * C + n] + (k == n ? c1 : 0.f);
    } else {
        int k2 = k - C;
        v = c4 * W2[k2 * C + n] + (k2 == n ? c3 : 0.f);
    }
    __nv_bfloat16 hi = __float2bfloat16_rn(v);
    g_MtH[i] = hi;
    g_MtL[i] = __float2bfloat16_rn(v - __bfloat162float(hi));
}

// Pre-split h0 into bf16 hi/lo
__global__ void split_h0_kernel(const float* __restrict__ h0, int total4) {
    int i = blockIdx.x * blockDim.x + threadIdx.x;
    if (i >= total4) return;
    float4 v = __ldg(&reinterpret_cast<const float4*>(h0)[i]);
    uint32_t h0w, l0w, h1w, l1w;
    split_pair(v.x, v.y, h0w, l0w);
    split_pair(v.z, v.w, h1w, l1w);
    reinterpret_cast<uint2*>(g_h0H)[i] = make_uint2(h0w, h1w);
    reinterpret_cast<uint2*>(g_h0L)[i] = make_uint2(l0w, l1w);
}

// ---------------------------------------------------------------------------
// CSR build: histogram (4-wide) -> 3-phase scan -> ticket scatter
// ---------------------------------------------------------------------------
__global__ void hist_kernel(const void* __restrict__ ei_raw, int E, int N) {
    const int is64 = g_is64;
    const long long* ei64 = (const long long*)ei_raw;
    const int*       ei32 = (const int*)ei_raw;
    int base   = (blockIdx.x * blockDim.x + threadIdx.x) * 4;
    int stride = gridDim.x * blockDim.x * 4;
    for (int e = base; e + 4 <= E; e += stride) {
        int r0, r1, r2, r3;
        if (is64) {
            longlong2 p0 = __ldg(reinterpret_cast<const longlong2*>(&ei64[e]));
            longlong2 p1 = __ldg(reinterpret_cast<const longlong2*>(&ei64[e + 2]));
            r0 = (int)p0.x; r1 = (int)p0.y; r2 = (int)p1.x; r3 = (int)p1.y;
        } else {
            int4 p = __ldg(reinterpret_cast<const int4*>(&ei32[e]));
            r0 = p.x; r1 = p.y; r2 = p.z; r3 = p.w;
        }
        if ((unsigned)r0 < (unsigned)N) atomicAdd(&g_cnt[r0], 1);
        if ((unsigned)r1 < (unsigned)N) atomicAdd(&g_cnt[r1], 1);
        if ((unsigned)r2 < (unsigned)N) atomicAdd(&g_cnt[r2], 1);
        if ((unsigned)r3 < (unsigned)N) atomicAdd(&g_cnt[r3], 1);
    }
    if (base == 0) {
        for (int e = E & ~3; e < E; e++) {
            int r = is64 ? (int)__ldg(&ei64[e]) : __ldg(&ei32[e]);
            if ((unsigned)r < (unsigned)N) atomicAdd(&g_cnt[r], 1);
        }
    }
}

__global__ void scan_p1(int N) {
    int j = blockIdx.x * blockDim.x + threadIdx.x;
    if (j >= NCH) return;
    int ch = (N + NCH - 1) / NCH;
    int s = j * ch, e = min(s + ch, N);
    int acc = 0;
    for (int i = s; i < e; i++) acc += g_cnt[i];
    g_psum[j] = acc;
}

__global__ void scan_p2() {
    __shared__ int sh[1024];
    int t = threadIdx.x;
    int loc[8];
    int s = 0;
    #pragma unroll
    for (int k = 0; k < 8; k++) { loc[k] = g_psum[t * 8 + k]; s += loc[k]; }
    sh[t] = s;
    __syncthreads();
    for (int off = 1; off < 1024; off <<= 1) {
        int add = (t >= off) ? sh[t - off] : 0;
        __syncthreads();
        sh[t] += add;
        __syncthreads();
    }
    int run = sh[t] - s;
    #pragma unroll
    for (int k = 0; k < 8; k++) { g_poff[t * 8 + k] = run; run += loc[k]; }
}

__global__ void scan_p3(int N, int E) {
    int j = blockIdx.x * blockDim.x + threadIdx.x;
    if (j >= NCH) return;
    int ch = (N + NCH - 1) / NCH;
    int s = j * ch, e = min(s + ch, N);
    int base = g_poff[j];
    for (int i = s; i < e; i++) {
        int c = g_cnt[i];
        g_rowstart[i] = base;
        g_cursor[i]   = base;
        base += c;
    }
    if (j == 0) g_rowstart[N] = E;
}

__global__ void scatter_kernel(const void* __restrict__ ei_raw,
                               const float* __restrict__ vals, int E, int N) {
    const int is64 = g_is64;
    const long long* ei64 = (const long long*)ei_raw;
    const int*       ei32 = (const int*)ei_raw;
    for (int e = blockIdx.x * blockDim.x + threadIdx.x; e < E;
         e += gridDim.x * blockDim.x) {
        int row, col;
        if (is64) {
            row = (int)__ldg(&ei64[e]);
            col = (int)__ldg(&ei64[(size_t)E + e]);
        } else {
            row = __ldg(&ei32[e]);
            col = __ldg(&ei32[(size_t)E + e]);
        }
        if ((unsigned)row >= (unsigned)N || (unsigned)col >= (unsigned)N) continue;
        int pos = atomicAdd(&g_cursor[row], 1);
        __stcs(&g_colval[pos],
               make_uint2((unsigned)col, __float_as_uint(__ldg(&vals[e]))));
    }
}

// ---------------------------------------------------------------------------
// SpMM over CSR: one warp per row; streaming colval loads; bf16 hi/lo stores.
// ---------------------------------------------------------------------------
__global__ __launch_bounds__(256)
void spmm_csr_kernel(const float* __restrict__ x, int N) {
    int warp = (blockIdx.x * blockDim.x + threadIdx.x) >> 5;
    int lane = threadIdx.x & 31;
    int nw   = (gridDim.x * blockDim.x) >> 5;
    for (int r = warp; r < N; r += nw) {
        int s = g_rowstart[r];
        int e = g_rowstart[r + 1];
        float4 acc0 = make_float4(0.f, 0.f, 0.f, 0.f);
        float4 acc1 = make_float4(0.f, 0.f, 0.f, 0.f);
        int i = s;
        for (; i + 2 <= e; i += 2) {
            uint2 cv0 = __ldcs(&g_colval[i]);
            uint2 cv1 = __ldcs(&g_colval[i + 1]);
            float v0 = __uint_as_float(cv0.y);
            float v1 = __uint_as_float(cv1.y);
            const float4* x0 = reinterpret_cast<const float4*>(x + (size_t)cv0.x * C);
            const float4* x1 = reinterpret_cast<const float4*>(x + (size_t)cv1.x * C);
            float4 a0 = __ldg(&x0[lane]),      b0 = __ldg(&x0[lane + 32]);
            float4 a1 = __ldg(&x1[lane]),      b1 = __ldg(&x1[lane + 32]);
            acc0.x += v0 * a0.x + v1 * a1.x;
            acc0.y += v0 * a0.y + v1 * a1.y;
            acc0.z += v0 * a0.z + v1 * a1.z;
            acc0.w += v0 * a0.w + v1 * a1.w;
            acc1.x += v0 * b0.x + v1 * b1.x;
            acc1.y += v0 * b0.y + v1 * b1.y;
            acc1.z += v0 * b0.z + v1 * b1.z;
            acc1.w += v0 * b0.w + v1 * b1.w;
        }
        if (i < e) {
            uint2 cv0 = __ldcs(&g_colval[i]);
            float v0 = __uint_as_float(cv0.y);
            const float4* x0 = reinterpret_cast<const float4*>(x + (size_t)cv0.x * C);
            float4 a0 = __ldg(&x0[lane]);
            float4 b0 = __ldg(&x0[lane + 32]);
            acc0.x += v0 * a0.x; acc0.y += v0 * a0.y;
            acc0.z += v0 * a0.z; acc0.w += v0 * a0.w;
            acc1.x += v0 * b0.x; acc1.y += v0 * b0.y;
            acc1.z += v0 * b0.z; acc1.w += v0 * b0.w;
        }
        uint32_t h0w, l0w, h1w, l1w;
        split_pair(acc0.x, acc0.y, h0w, l0w);
        split_pair(acc0.z, acc0.w, h1w, l1w);
        uint2* dH = reinterpret_cast<uint2*>(g_axH + (size_t)r * C + lane * 4);
        uint2* dL = reinterpret_cast<uint2*>(g_axL + (size_t)r * C + lane * 4);
        __stcs(dH, make_uint2(h0w, h1w));
        __stcs(dL, make_uint2(l0w, l1w));
        split_pair(acc1.x, acc1.y, h0w, l0w);
        split_pair(acc1.z, acc1.w, h1w, l1w);
        dH = reinterpret_cast<uint2*>(g_axH + (size_t)r * C + 128 + lane * 4);
        dL = reinterpret_cast<uint2*>(g_axL + (size_t)r * C + 128 + lane * 4);
        __stcs(dH, make_uint2(h0w, h1w));
        __stcs(dL, make_uint2(l0w, l1w));
    }
}

// ---------------------------------------------------------------------------
// Merged tensor-core GEMM: out[N,256] = [ax|h0] @ M (K=512), bf16 hi/lo.
// Tile 128x64, BK=32, 8 warps of 32x32, 3 CTAs/SM for occupancy.
// ---------------------------------------------------------------------------
#define BM 128
#define BN 64
#define BK 32
#define LDS_W 20                          // words/row: 16 data + 4 pad
#define A_ARR_W (128 * LDS_W)             // 2560 words
#define B_ARR_W (64 * LDS_W)              // 1280 words
#define STG_W (2 * A_ARR_W + 2 * B_ARR_W) // 7680 words = 30720 B
#define SMEM_BYTES (2 * STG_W * 4)        // 61440 B

__device__ __forceinline__ uint32_t s2u(const void* p) {
    uint32_t a;
    asm("{ .reg .u64 t; cvta.to.shared.u64 t, %1; cvt.u32.u64 %0, t; }"
        : "=r"(a) : "l"(p));
    return a;
}
__device__ __forceinline__ void cp16(uint32_t daddr, const void* g) {
    asm volatile("cp.async.cg.shared.global [%0], [%1], 16;"
                 :: "r"(daddr), "l"(g));
}
__device__ __forceinline__ void cp16z(uint32_t daddr, const void* g) {
    asm volatile("cp.async.cg.shared.global [%0], [%1], 16, 0;"
                 :: "r"(daddr), "l"(g));
}
__device__ __forceinline__ void cp_commit() {
    asm volatile("cp.async.commit_group;");
}
__device__ __forceinline__ void cp_wait0() {
    asm volatile("cp.async.wait_group 0;");
}
__device__ __forceinline__ void ldm_x4(uint32_t* r, uint32_t addr) {
    asm volatile("ldmatrix.sync.aligned.m8n8.x4.shared.b16 {%0,%1,%2,%3}, [%4];"
                 : "=r"(r[0]), "=r"(r[1]), "=r"(r[2]), "=r"(r[3]) : "r"(addr));
}
__device__ __forceinline__ void mma_bf16(float* c, const uint32_t* a,
                                         uint32_t b0, uint32_t b1) {
    asm volatile(
        "mma.sync.aligned.m16n8k16.row.col.f32.bf16.bf16.f32 "
        "{%0,%1,%2,%3}, {%4,%5,%6,%7}, {%8,%9}, {%0,%1,%2,%3};"
        : "+f"(c[0]), "+f"(c[1]), "+f"(c[2]), "+f"(c[3])
        : "r"(a[0]), "r"(a[1]), "r"(a[2]), "r"(a[3]), "r"(b0), "r"(b1));
}

__global__ __launch_bounds__(256, 3)
void gemm_bf16_kernel(float* __restrict__ out, int N) {
    extern __shared__ uint32_t smem[];
    const uint32_t sbase = s2u(smem);

    const int tid  = threadIdx.x;
    const int lane = tid & 31;
    const int wid  = tid >> 5;
    const int warp_m = (wid & 3) * 32;
    const int warp_n = (wid >> 2) * 32;
    const int bn = blockIdx.x * BN;    // x fastest -> bn-siblings co-resident
    const int bm = blockIdx.y * BM;

    const int a_row = (lane & 7) + ((lane >> 3) & 1) * 8;
    const int a_k   = (lane >> 4) * 8;
    const int b_row = (lane & 7) + (lane >> 4) * 8;
    const int b_k   = ((lane >> 3) & 1) * 8;

    float acc[2][4][4];   // mt x (ntp*2+j) x quad
    #pragma unroll
    for (int i = 0; i < 2; i++)
        #pragma unroll
        for (int j = 0; j < 4; j++)
            #pragma unroll
            for (int q = 0; q < 4; q++) acc[i][j][q] = 0.f;

    // A loader mapping: 256 thr -> 128 rows x 2 halves (32B each)
    const int lrow = tid >> 1;
    const int lh   = tid & 1;
    const int arow = bm + lrow;
    const bool avalid = (arow < N);
    const int acl = avalid ? arow : 0;
    // B loader mapping: 256 thr -> 64 rows x 4 quarters (16B each)
    const int brow = tid >> 2;
    const int bq   = tid & 3;

    const int T = KTOT / BK;   // 16 tiles

    auto load_tile = [&](int t, int stg) {
        const int kt = t * BK;
        const size_t aoff = (size_t)acl * C + ((kt < C) ? kt : kt - C) + lh * 16;
        const __nv_bfloat16* gAH = (kt < C) ? (g_axH + aoff) : (g_h0H + aoff);
        const __nv_bfloat16* gAL = (kt < C) ? (g_axL + aoff) : (g_h0L + aoff);
        uint32_t drow = sbase + (stg * STG_W + lrow * LDS_W + lh * 8) * 4;
        #pragma unroll
        for (int c = 0; c < 2; c++) {
            if (avalid) {
                cp16(drow + c * 16,                 gAH + c * 8);
                cp16(drow + A_ARR_W * 4 + c * 16,   gAL + c * 8);
            } else {
                cp16z(drow + c * 16,                gAH + c * 8);
                cp16z(drow + A_ARR_W * 4 + c * 16,  gAL + c * 8);
            }
        }
        const size_t boff = (size_t)(bn + brow) * KTOT + kt + bq * 8;
        uint32_t db = sbase + (stg * STG_W + 2 * A_ARR_W + brow * LDS_W + bq * 4) * 4;
        cp16(db,                 g_MtH + boff);
        cp16(db + B_ARR_W * 4,   g_MtL + boff);
        cp_commit();
    };

    load_tile(0, 0);

    for (int t = 0; t < T; t++) {
        cp_wait0();
        __syncthreads();
        if (t + 1 < T) load_tile(t + 1, (t + 1) & 1);

        const int stg = t & 1;
        const uint32_t aH0 = sbase + (stg * STG_W) * 4;
        const uint32_t aL0 = aH0 + A_ARR_W * 4;
        const uint32_t bH0 = aH0 + 2 * A_ARR_W * 4;
        const uint32_t bL0 = bH0 + B_ARR_W * 4;

        #pragma unroll
        for (int ks = 0; ks < 2; ks++) {
            const int kk = ks * 16;
            uint32_t aH[2][4], aL[2][4];
            #pragma unroll
            for (int mt = 0; mt < 2; mt++) {
                uint32_t off = ((warp_m + mt * 16 + a_row) * LDS_W) * 4
                             + (kk + a_k) * 2;
                ldm_x4(aH[mt], aH0 + off);
                ldm_x4(aL[mt], aL0 + off);
            }
            #pragma unroll
            for (int ntp = 0; ntp < 2; ntp++) {
                uint32_t bH[4], bL[4];
                uint32_t off = ((warp_n + ntp * 16 + b_row) * LDS_W) * 4
                             + (kk + b_k) * 2;
                ldm_x4(bH, bH0 + off);
                ldm_x4(bL, bL0 + off);
                #pragma unroll
                for (int mt = 0; mt < 2; mt++) {
                    #pragma unroll
                    for (int j = 0; j < 2; j++) {
                        float* c = acc[mt][ntp * 2 + j];
                        mma_bf16(c, aH[mt], bH[2*j], bH[2*j+1]);
                        mma_bf16(c, aH[mt], bL[2*j], bL[2*j+1]);
                        mma_bf16(c, aL[mt], bH[2*j], bH[2*j+1]);
                    }
                }
            }
        }
        __syncthreads();
    }

    #pragma unroll
    for (int mt = 0; mt < 2; mt++) {
        #pragma unroll
        for (int nt = 0; nt < 4; nt++) {
            int r0  = bm + warp_m + mt * 16 + (lane >> 2);
            int col = bn + warp_n + nt * 8 + (lane & 3) * 2;
            if (r0 < N)
                *reinterpret_cast<float2*>(out + (size_t)r0 * C + col) =
                    make_float2(acc[mt][nt][0], acc[mt][nt][1]);
            int r1 = r0 + 8;
            if (r1 < N)
                *reinterpret_cast<float2*>(out + (size_t)r1 * C + col) =
                    make_float2(acc[mt][nt][2], acc[mt][nt][3]);
        }
    }
}

// ---------------------------------------------------------------------------
// Launch (serial; split/overlap reverted after R9 regression)
// ---------------------------------------------------------------------------
extern "C" void kernel_launch(void* const* d_in, const int* in_sizes, int n_in,
                              void* d_out, int out_size) {
    const float* x    = (const float*)d_in[0];
    const float* vals = (const float*)d_in[1];
    const void*  ei   = d_in[2];
    const float* h0   = (const float*)d_in[3];
    const float* W1   = (const float*)d_in[4];
    const float* W2   = (const float*)d_in[5];
    const float* pa   = (const float*)d_in[6];
    const float* pb   = (const float*)d_in[7];
    float* out = (float*)d_out;

    const int N = in_sizes[0] / C;     // 100000
    int E = in_sizes[1];               // 3200000
    if (E > MAXE) E = MAXE;

    static bool inited = false;
    if (!inited) {
        cudaFuncSetAttribute(gemm_bf16_kernel,
                             cudaFuncAttributeMaxDynamicSharedMemorySize,
                             SMEM_BYTES);
        inited = true;
    }

    detect_idx_kernel<<<1, 32>>>((const int*)ei, in_sizes[2]);
    build_Mt_kernel<<<(C * KTOT + 255) / 256, 256>>>(W1, W2, pa, pb);
    int total4 = N * C / 4;
    split_h0_kernel<<<(total4 + 255) / 256, 256>>>(h0, total4);

    zero_cnt_kernel<<<(N + 255) / 256, 256>>>(N);
    hist_kernel<<<3125, 256>>>(ei, E, N);
    scan_p1<<<NCH / 256, 256>>>(N);
    scan_p2<<<1, 1024>>>();
    scan_p3<<<NCH / 256, 256>>>(N, E);
    scatter_kernel<<<4096, 256>>>(ei, vals, E, N);

    int spmm_blocks = (N * 32 + 255) / 256;
    spmm_csr_kernel<<<spmm_blocks, 256>>>(x, N);

    dim3 grid(C / BN, (N + BM - 1) / BM);   // (4, 782)
    gemm_bf16_kernel<<<grid, 256, SMEM_BYTES>>>(out, N);
}

// round 11
// speedup vs baseline: 1.3955x; 1.3128x over previous
#include <cuda_runtime.h>
#include <cuda_bf16.h>
#include <cuda_fp16.h>
#include <cstdint>

#define C 256
#define MAXN 100000
#define MAXE 3200000
#define KTOT 512
#define NCH  8192   // scan chunks

// Scratch (__device__ globals; allocation-free rule)
__device__ __align__(256) __half        g_xh[(size_t)MAXN * C];   // fp16 copy of x
__device__ __align__(256) __nv_bfloat16 g_axH[(size_t)MAXN * C];
__device__ __align__(256) __nv_bfloat16 g_axL[(size_t)MAXN * C];
__device__ __align__(256) __nv_bfloat16 g_h0H[(size_t)MAXN * C];
__device__ __align__(256) __nv_bfloat16 g_h0L[(size_t)MAXN * C];
__device__ __align__(256) __nv_bfloat16 g_MtH[C * KTOT];   // M^T hi, [n][k]
__device__ __align__(256) __nv_bfloat16 g_MtL[C * KTOT];   // M^T lo, [n][k]
__device__ int   g_is64;
__device__ int   g_cnt[MAXN];
__device__ int   g_rowstart[MAXN + 1];
__device__ int   g_cursor[MAXN];
__device__ __align__(16) uint2 g_colval[MAXE];             // interleaved CSR
__device__ int   g_psum[NCH];
__device__ int   g_poff[NCH];

// ---------------------------------------------------------------------------
__device__ __forceinline__ void split_pair(float x, float y,
                                           uint32_t& hi, uint32_t& lo) {
    __nv_bfloat162 h = __floats2bfloat162_rn(x, y);
    float hx = __bfloat162float(__low2bfloat16(h));
    float hy = __bfloat162float(__high2bfloat16(h));
    __nv_bfloat162 l = __floats2bfloat162_rn(x - hx, y - hy);
    hi = *reinterpret_cast<uint32_t*>(&h);
    lo = *reinterpret_cast<uint32_t*>(&l);
}

// ---------------------------------------------------------------------------
__global__ void detect_idx_kernel(const int* __restrict__ ei32, int nwords) {
    if (threadIdx.x != 0 || blockIdx.x != 0) return;
    int nonzero_odd = 0;
    int lim = nwords < 1024 ? nwords : 1024;
    for (int i = 1; i < lim; i += 2) nonzero_odd += (ei32[i] != 0);
    g_is64 = (nonzero_odd == 0) ? 1 : 0;
}

__global__ void zero_cnt_kernel(int N) {
    int i = blockIdx.x * blockDim.x + threadIdx.x;
    if (i < N) g_cnt[i] = 0;
}

// fp16 copy of x (one 16B store per 8 elements)
__global__ void cvt_x_kernel(const float* __restrict__ x, int total8) {
    int i = blockIdx.x * blockDim.x + threadIdx.x;
    if (i >= total8) return;
    const float4* p = reinterpret_cast<const float4*>(x) + (size_t)i * 2;
    float4 a = __ldg(p);
    float4 b = __ldg(p + 1);
    __half2 h0 = __floats2half2_rn(a.x, a.y);
    __half2 h1 = __floats2half2_rn(a.z, a.w);
    __half2 h2 = __floats2half2_rn(b.x, b.y);
    __half2 h3 = __floats2half2_rn(b.z, b.w);
    uint4 o;
    o.x = *reinterpret_cast<uint32_t*>(&h0);
    o.y = *reinterpret_cast<uint32_t*>(&h1);
    o.z = *reinterpret_cast<uint32_t*>(&h2);
    o.w = *reinterpret_cast<uint32_t*>(&h3);
    reinterpret_cast<uint4*>(g_xh)[i] = o;
}

// Build transposed+split blend matrix g_Mt[n][k]
__global__ void build_Mt_kernel(const float* __restrict__ W1,
                                const float* __restrict__ W2,
                                const float* __restrict__ p_alpha,
                                const float* __restrict__ p_beta) {
    float a = *p_alpha, b = *p_beta;
    float c1 = (1.f - a) * (1.f - b);
    float c2 = (1.f - a) * b;
    float c3 = a * (1.f - b);
    float c4 = a * b;
    int i = blockIdx.x * blockDim.x + threadIdx.x;
    if (i >= C * KTOT) return;
    int n = i / KTOT, k = i % KTOT;
    float v;
    if (k < C) {
        v = c2 * W1[k * C + n] + (k == n ? c1 : 0.f);
    } else {
        int k2 = k - C;
        v = c4 * W2[k2 * C + n] + (k2 == n ? c3 : 0.f);
    }
    __nv_bfloat16 hi = __float2bfloat16_rn(v);
    g_MtH[i] = hi;
    g_MtL[i] = __float2bfloat16_rn(v - __bfloat162float(hi));
}

// Pre-split h0 into bf16 hi/lo
__global__ void split_h0_kernel(const float* __restrict__ h0, int total4) {
    int i = blockIdx.x * blockDim.x + threadIdx.x;
    if (i >= total4) return;
    float4 v = __ldg(&reinterpret_cast<const float4*>(h0)[i]);
    uint32_t h0w, l0w, h1w, l1w;
    split_pair(v.x, v.y, h0w, l0w);
    split_pair(v.z, v.w, h1w, l1w);
    reinterpret_cast<uint2*>(g_h0H)[i] = make_uint2(h0w, h1w);
    reinterpret_cast<uint2*>(g_h0L)[i] = make_uint2(l0w, l1w);
}

// ---------------------------------------------------------------------------
// CSR build: histogram (4-wide) -> 3-phase scan -> ticket scatter
// ---------------------------------------------------------------------------
__global__ void hist_kernel(const void* __restrict__ ei_raw, int E, int N) {
    const int is64 = g_is64;
    const long long* ei64 = (const long long*)ei_raw;
    const int*       ei32 = (const int*)ei_raw;
    int base   = (blockIdx.x * blockDim.x + threadIdx.x) * 4;
    int stride = gridDim.x * blockDim.x * 4;
    for (int e = base; e + 4 <= E; e += stride) {
        int r0, r1, r2, r3;
        if (is64) {
            longlong2 p0 = __ldg(reinterpret_cast<const longlong2*>(&ei64[e]));
            longlong2 p1 = __ldg(reinterpret_cast<const longlong2*>(&ei64[e + 2]));
            r0 = (int)p0.x; r1 = (int)p0.y; r2 = (int)p1.x; r3 = (int)p1.y;
        } else {
            int4 p = __ldg(reinterpret_cast<const int4*>(&ei32[e]));
            r0 = p.x; r1 = p.y; r2 = p.z; r3 = p.w;
        }
        if ((unsigned)r0 < (unsigned)N) atomicAdd(&g_cnt[r0], 1);
        if ((unsigned)r1 < (unsigned)N) atomicAdd(&g_cnt[r1], 1);
        if ((unsigned)r2 < (unsigned)N) atomicAdd(&g_cnt[r2], 1);
        if ((unsigned)r3 < (unsigned)N) atomicAdd(&g_cnt[r3], 1);
    }
    if (base == 0) {
        for (int e = E & ~3; e < E; e++) {
            int r = is64 ? (int)__ldg(&ei64[e]) : __ldg(&ei32[e]);
            if ((unsigned)r < (unsigned)N) atomicAdd(&g_cnt[r], 1);
        }
    }
}

__global__ void scan_p1(int N) {
    int j = blockIdx.x * blockDim.x + threadIdx.x;
    if (j >= NCH) return;
    int ch = (N + NCH - 1) / NCH;
    int s = j * ch, e = min(s + ch, N);
    int acc = 0;
    for (int i = s; i < e; i++) acc += g_cnt[i];
    g_psum[j] = acc;
}

__global__ void scan_p2() {
    __shared__ int sh[1024];
    int t = threadIdx.x;
    int loc[8];
    int s = 0;
    #pragma unroll
    for (int k = 0; k < 8; k++) { loc[k] = g_psum[t * 8 + k]; s += loc[k]; }
    sh[t] = s;
    __syncthreads();
    for (int off = 1; off < 1024; off <<= 1) {
        int add = (t >= off) ? sh[t - off] : 0;
        __syncthreads();
        sh[t] += add;
        __syncthreads();
    }
    int run = sh[t] - s;
    #pragma unroll
    for (int k = 0; k < 8; k++) { g_poff[t * 8 + k] = run; run += loc[k]; }
}

__global__ void scan_p3(int N, int E) {
    int j = blockIdx.x * blockDim.x + threadIdx.x;
    if (j >= NCH) return;
    int ch = (N + NCH - 1) / NCH;
    int s = j * ch, e = min(s + ch, N);
    int base = g_poff[j];
    for (int i = s; i < e; i++) {
        int c = g_cnt[i];
        g_rowstart[i] = base;
        g_cursor[i]   = base;
        base += c;
    }
    if (j == 0) g_rowstart[N] = E;
}

__global__ void scatter_kernel(const void* __restrict__ ei_raw,
                               const float* __restrict__ vals, int E, int N) {
    const int is64 = g_is64;
    const long long* ei64 = (const long long*)ei_raw;
    const int*       ei32 = (const int*)ei_raw;
    for (int e = blockIdx.x * blockDim.x + threadIdx.x; e < E;
         e += gridDim.x * blockDim.x) {
        int row, col;
        if (is64) {
            row = (int)__ldg(&ei64[e]);
            col = (int)__ldg(&ei64[(size_t)E + e]);
        } else {
            row = __ldg(&ei32[e]);
            col = __ldg(&ei32[(size_t)E + e]);
        }
        if ((unsigned)row >= (unsigned)N || (unsigned)col >= (unsigned)N) continue;
        int pos = atomicAdd(&g_cursor[row], 1);
        __stcs(&g_colval[pos],
               make_uint2((unsigned)col, __float_as_uint(__ldg(&vals[e]))));
    }
}

// ---------------------------------------------------------------------------
// SpMM over CSR: one warp per row; fp16 x gathers (16B/lane), 4-edge unroll;
// fp32 accumulate; epilogue stores bf16 hi/lo (uint4 streaming stores).
// ---------------------------------------------------------------------------
__device__ __forceinline__ void accum8(float* acc, uint4 a, float v) {
    __half2* h = reinterpret_cast<__half2*>(&a);
    #pragma unroll
    for (int q = 0; q < 4; q++) {
        float2 f = __half22float2(h[q]);
        acc[2 * q]     += v * f.x;
        acc[2 * q + 1] += v * f.y;
    }
}

__global__ __launch_bounds__(256)
void spmm_csr_kernel(int N) {
    int warp = (blockIdx.x * blockDim.x + threadIdx.x) >> 5;
    int lane = threadIdx.x & 31;
    int nw   = (gridDim.x * blockDim.x) >> 5;
    for (int r = warp; r < N; r += nw) {
        int s = g_rowstart[r];
        int e = g_rowstart[r + 1];
        float acc[8];
        #pragma unroll
        for (int q = 0; q < 8; q++) acc[q] = 0.f;
        int i = s;
        for (; i + 4 <= e; i += 4) {
            uint2 cv0 = __ldcs(&g_colval[i]);
            uint2 cv1 = __ldcs(&g_colval[i + 1]);
            uint2 cv2 = __ldcs(&g_colval[i + 2]);
            uint2 cv3 = __ldcs(&g_colval[i + 3]);
            uint4 a0 = __ldg(reinterpret_cast<const uint4*>(
                                 g_xh + (size_t)cv0.x * C) + lane);
            uint4 a1 = __ldg(reinterpret_cast<const uint4*>(
                                 g_xh + (size_t)cv1.x * C) + lane);
            uint4 a2 = __ldg(reinterpret_cast<const uint4*>(
                                 g_xh + (size_t)cv2.x * C) + lane);
            uint4 a3 = __ldg(reinterpret_cast<const uint4*>(
                                 g_xh + (size_t)cv3.x * C) + lane);
            accum8(acc, a0, __uint_as_float(cv0.y));
            accum8(acc, a1, __uint_as_float(cv1.y));
            accum8(acc, a2, __uint_as_float(cv2.y));
            accum8(acc, a3, __uint_as_float(cv3.y));
        }
        for (; i < e; i++) {
            uint2 cv0 = __ldcs(&g_colval[i]);
            uint4 a0 = __ldg(reinterpret_cast<const uint4*>(
                                 g_xh + (size_t)cv0.x * C) + lane);
            accum8(acc, a0, __uint_as_float(cv0.y));
        }
        // split + streaming store: lane covers cols [8*lane, 8*lane+8)
        uint32_t H[4], L[4];
        split_pair(acc[0], acc[1], H[0], L[0]);
        split_pair(acc[2], acc[3], H[1], L[1]);
        split_pair(acc[4], acc[5], H[2], L[2]);
        split_pair(acc[6], acc[7], H[3], L[3]);
        __stcs(reinterpret_cast<uint4*>(g_axH + (size_t)r * C + lane * 8),
               make_uint4(H[0], H[1], H[2], H[3]));
        __stcs(reinterpret_cast<uint4*>(g_axL + (size_t)r * C + lane * 8),
               make_uint4(L[0], L[1], L[2], L[3]));
    }
}

// ---------------------------------------------------------------------------
// Merged tensor-core GEMM: out[N,256] = [ax|h0] @ M (K=512), bf16 hi/lo.
// Tile 128x64, BK=32, 8 warps of 32x32, 3 CTAs/SM.
// ---------------------------------------------------------------------------
#define BM 128
#define BN 64
#define BK 32
#define LDS_W 20                          // words/row: 16 data + 4 pad
#define A_ARR_W (128 * LDS_W)             // 2560 words
#define B_ARR_W (64 * LDS_W)              // 1280 words
#define STG_W (2 * A_ARR_W + 2 * B_ARR_W) // 7680 words = 30720 B
#define SMEM_BYTES (2 * STG_W * 4)        // 61440 B

__device__ __forceinline__ uint32_t s2u(const void* p) {
    uint32_t a;
    asm("{ .reg .u64 t; cvta.to.shared.u64 t, %1; cvt.u32.u64 %0, t; }"
        : "=r"(a) : "l"(p));
    return a;
}
__device__ __forceinline__ void cp16(uint32_t daddr, const void* g) {
    asm volatile("cp.async.cg.shared.global [%0], [%1], 16;"
                 :: "r"(daddr), "l"(g));
}
__device__ __forceinline__ void cp16z(uint32_t daddr, const void* g) {
    asm volatile("cp.async.cg.shared.global [%0], [%1], 16, 0;"
                 :: "r"(daddr), "l"(g));
}
__device__ __forceinline__ void cp_commit() {
    asm volatile("cp.async.commit_group;");
}
__device__ __forceinline__ void cp_wait0() {
    asm volatile("cp.async.wait_group 0;");
}
__device__ __forceinline__ void ldm_x4(uint32_t* r, uint32_t addr) {
    asm volatile("ldmatrix.sync.aligned.m8n8.x4.shared.b16 {%0,%1,%2,%3}, [%4];"
                 : "=r"(r[0]), "=r"(r[1]), "=r"(r[2]), "=r"(r[3]) : "r"(addr));
}
__device__ __forceinline__ void mma_bf16(float* c, const uint32_t* a,
                                         uint32_t b0, uint32_t b1) {
    asm volatile(
        "mma.sync.aligned.m16n8k16.row.col.f32.bf16.bf16.f32 "
        "{%0,%1,%2,%3}, {%4,%5,%6,%7}, {%8,%9}, {%0,%1,%2,%3};"
        : "+f"(c[0]), "+f"(c[1]), "+f"(c[2]), "+f"(c[3])
        : "r"(a[0]), "r"(a[1]), "r"(a[2]), "r"(a[3]), "r"(b0), "r"(b1));
}

__global__ __launch_bounds__(256, 3)
void gemm_bf16_kernel(float* __restrict__ out, int N) {
    extern __shared__ uint32_t smem[];
    const uint32_t sbase = s2u(smem);

    const int tid  = threadIdx.x;
    const int lane = tid & 31;
    const int wid  = tid >> 5;
    const int warp_m = (wid & 3) * 32;
    const int warp_n = (wid >> 2) * 32;
    const int bn = blockIdx.x * BN;
    const int bm = blockIdx.y * BM;

    const int a_row = (lane & 7) + ((lane >> 3) & 1) * 8;
    const int a_k   = (lane >> 4) * 8;
    const int b_row = (lane & 7) + (lane >> 4) * 8;
    const int b_k   = ((lane >> 3) & 1) * 8;

    float acc[2][4][4];
    #pragma unroll
    for (int i = 0; i < 2; i++)
        #pragma unroll
        for (int j = 0; j < 4; j++)
            #pragma unroll
            for (int q = 0; q < 4; q++) acc[i][j][q] = 0.f;

    const int lrow = tid >> 1;
    const int lh   = tid & 1;
    const int arow = bm + lrow;
    const bool avalid = (arow < N);
    const int acl = avalid ? arow : 0;
    const int brow = tid >> 2;
    const int bq   = tid & 3;

    const int T = KTOT / BK;

    auto load_tile = [&](int t, int stg) {
        const int kt = t * BK;
        const size_t aoff = (size_t)acl * C + ((kt < C) ? kt : kt - C) + lh * 16;
        const __nv_bfloat16* gAH = (kt < C) ? (g_axH + aoff) : (g_h0H + aoff);
        const __nv_bfloat16* gAL = (kt < C) ? (g_axL + aoff) : (g_h0L + aoff);
        uint32_t drow = sbase + (stg * STG_W + lrow * LDS_W + lh * 8) * 4;
        #pragma unroll
        for (int c = 0; c < 2; c++) {
            if (avalid) {
                cp16(drow + c * 16,                 gAH + c * 8);
                cp16(drow + A_ARR_W * 4 + c * 16,   gAL + c * 8);
            } else {
                cp16z(drow + c * 16,                gAH + c * 8);
                cp16z(drow + A_ARR_W * 4 + c * 16,  gAL + c * 8);
            }
        }
        const size_t boff = (size_t)(bn + brow) * KTOT + kt + bq * 8;
        uint32_t db = sbase + (stg * STG_W + 2 * A_ARR_W + brow * LDS_W + bq * 4) * 4;
        cp16(db,                 g_MtH + boff);
        cp16(db + B_ARR_W * 4,   g_MtL + boff);
        cp_commit();
    };

    load_tile(0, 0);

    for (int t = 0; t < T; t++) {
        cp_wait0();
        __syncthreads();
        if (t + 1 < T) load_tile(t + 1, (t + 1) & 1);

        const int stg = t & 1;
        const uint32_t aH0 = sbase + (stg * STG_W) * 4;
        const uint32_t aL0 = aH0 + A_ARR_W * 4;
        const uint32_t bH0 = aH0 + 2 * A_ARR_W * 4;
        const uint32_t bL0 = bH0 + B_ARR_W * 4;

        #pragma unroll
        for (int ks = 0; ks < 2; ks++) {
            const int kk = ks * 16;
            uint32_t aH[2][4], aL[2][4];
            #pragma unroll
            for (int mt = 0; mt < 2; mt++) {
                uint32_t off = ((warp_m + mt * 16 + a_row) * LDS_W) * 4
                             + (kk + a_k) * 2;
                ldm_x4(aH[mt], aH0 + off);
                ldm_x4(aL[mt], aL0 + off);
            }
            #pragma unroll
            for (int ntp = 0; ntp < 2; ntp++) {
                uint32_t bH[4], bL[4];
                uint32_t off = ((warp_n + ntp * 16 + b_row) * LDS_W) * 4
                             + (kk + b_k) * 2;
                ldm_x4(bH, bH0 + off);
                ldm_x4(bL, bL0 + off);
                #pragma unroll
                for (int mt = 0; mt < 2; mt++) {
                    #pragma unroll
                    for (int j = 0; j < 2; j++) {
                        float* c = acc[mt][ntp * 2 + j];
                        mma_bf16(c, aH[mt], bH[2*j], bH[2*j+1]);
                        mma_bf16(c, aH[mt], bL[2*j], bL[2*j+1]);
                        mma_bf16(c, aL[mt], bH[2*j], bH[2*j+1]);
                    }
                }
            }
        }
        __syncthreads();
    }

    #pragma unroll
    for (int mt = 0; mt < 2; mt++) {
        #pragma unroll
        for (int nt = 0; nt < 4; nt++) {
            int r0  = bm + warp_m + mt * 16 + (lane >> 2);
            int col = bn + warp_n + nt * 8 + (lane & 3) * 2;
            if (r0 < N)
                *reinterpret_cast<float2*>(out + (size_t)r0 * C + col) =
                    make_float2(acc[mt][nt][0], acc[mt][nt][1]);
            int r1 = r0 + 8;
            if (r1 < N)
                *reinterpret_cast<float2*>(out + (size_t)r1 * C + col) =
                    make_float2(acc[mt][nt][2], acc[mt][nt][3]);
        }
    }
}

// ---------------------------------------------------------------------------
// Launch (serial single stream)
// ---------------------------------------------------------------------------
extern "C" void kernel_launch(void* const* d_in, const int* in_sizes, int n_in,
                              void* d_out, int out_size) {
    const float* x    = (const float*)d_in[0];
    const float* vals = (const float*)d_in[1];
    const void*  ei   = d_in[2];
    const float* h0   = (const float*)d_in[3];
    const float* W1   = (const float*)d_in[4];
    const float* W2   = (const float*)d_in[5];
    const float* pa   = (const float*)d_in[6];
    const float* pb   = (const float*)d_in[7];
    float* out = (float*)d_out;

    const int N = in_sizes[0] / C;     // 100000
    int E = in_sizes[1];               // 3200000
    if (E > MAXE) E = MAXE;

    static bool inited = false;
    if (!inited) {
        cudaFuncSetAttribute(gemm_bf16_kernel,
                             cudaFuncAttributeMaxDynamicSharedMemorySize,
                             SMEM_BYTES);
        inited = true;
    }

    detect_idx_kernel<<<1, 32>>>((const int*)ei, in_sizes[2]);
    int total8 = N * C / 8;
    cvt_x_kernel<<<(total8 + 255) / 256, 256>>>(x, total8);
    build_Mt_kernel<<<(C * KTOT + 255) / 256, 256>>>(W1, W2, pa, pb);
    int total4 = N * C / 4;
    split_h0_kernel<<<(total4 + 255) / 256, 256>>>(h0, total4);

    zero_cnt_kernel<<<(N + 255) / 256, 256>>>(N);
    hist_kernel<<<3125, 256>>>(ei, E, N);
    scan_p1<<<NCH / 256, 256>>>(N);
    scan_p2<<<1, 1024>>>();
    scan_p3<<<NCH / 256, 256>>>(N, E);
    scatter_kernel<<<4096, 256>>>(ei, vals, E, N);

    int spmm_blocks = (N * 32 + 255) / 256;
    spmm_csr_kernel<<<spmm_blocks, 256>>>(N);

    dim3 grid(C / BN, (N + BM - 1) / BM);   // (4, 782)
    gemm_bf16_kernel<<<grid, 256, SMEM_BYTES>>>(out, N);
}

// round 12
// speedup vs baseline: 1.7062x; 1.2227x over previous
#include <cuda_runtime.h>
#include <cuda_fp16.h>
#include <cstdint>

#define C 256
#define MAXN 100000
#define MAXE 3200000
#define KTOT 512
#define NCH  8192   // scan chunks

// Scratch (__device__ globals; allocation-free rule)
__device__ __align__(256) __half g_xh[(size_t)MAXN * C];    // fp16 x
__device__ __align__(256) __half g_axh[(size_t)MAXN * C];   // fp16 A@x
__device__ __align__(256) __half g_h0h[(size_t)MAXN * C];   // fp16 h0
__device__ __align__(256) __half g_Mth[C * KTOT];           // fp16 M^T [n][k]
__device__ int   g_is64;
__device__ int   g_cnt[MAXN];
__device__ int   g_rowstart[MAXN + 1];
__device__ int   g_cursor[MAXN];
__device__ __align__(16) uint2 g_colval[MAXE];              // interleaved CSR
__device__ int   g_psum[NCH];
__device__ int   g_poff[NCH];

// ---------------------------------------------------------------------------
__global__ void detect_idx_kernel(const int* __restrict__ ei32, int nwords) {
    if (threadIdx.x != 0 || blockIdx.x != 0) return;
    int nonzero_odd = 0;
    int lim = nwords < 1024 ? nwords : 1024;
    for (int i = 1; i < lim; i += 2) nonzero_odd += (ei32[i] != 0);
    g_is64 = (nonzero_odd == 0) ? 1 : 0;
}

__global__ void zero_cnt_kernel(int N) {
    int i = blockIdx.x * blockDim.x + threadIdx.x;
    if (i < N) g_cnt[i] = 0;
}

// fp32 -> fp16 copy (8 elements / thread, 16B store)
__global__ void cvt_f16_kernel(const float* __restrict__ src,
                               __half* __restrict__ dst, int total8) {
    int i = blockIdx.x * blockDim.x + threadIdx.x;
    if (i >= total8) return;
    const float4* p = reinterpret_cast<const float4*>(src) + (size_t)i * 2;
    float4 a = __ldg(p);
    float4 b = __ldg(p + 1);
    __half2 h0 = __floats2half2_rn(a.x, a.y);
    __half2 h1 = __floats2half2_rn(a.z, a.w);
    __half2 h2 = __floats2half2_rn(b.x, b.y);
    __half2 h3 = __floats2half2_rn(b.z, b.w);
    uint4 o;
    o.x = *reinterpret_cast<uint32_t*>(&h0);
    o.y = *reinterpret_cast<uint32_t*>(&h1);
    o.z = *reinterpret_cast<uint32_t*>(&h2);
    o.w = *reinterpret_cast<uint32_t*>(&h3);
    reinterpret_cast<uint4*>(dst)[i] = o;
}

// wrappers so host never takes a __device__ symbol address (R8 lesson)
__global__ void cvt_x_kernel(const float* __restrict__ x, int total8) {
    int i = blockIdx.x * blockDim.x + threadIdx.x;
    if (i >= total8) return;
    const float4* p = reinterpret_cast<const float4*>(x) + (size_t)i * 2;
    float4 a = __ldg(p);
    float4 b = __ldg(p + 1);
    __half2 h0 = __floats2half2_rn(a.x, a.y);
    __half2 h1 = __floats2half2_rn(a.z, a.w);
    __half2 h2 = __floats2half2_rn(b.x, b.y);
    __half2 h3 = __floats2half2_rn(b.z, b.w);
    uint4 o;
    o.x = *reinterpret_cast<uint32_t*>(&h0);
    o.y = *reinterpret_cast<uint32_t*>(&h1);
    o.z = *reinterpret_cast<uint32_t*>(&h2);
    o.w = *reinterpret_cast<uint32_t*>(&h3);
    reinterpret_cast<uint4*>(g_xh)[i] = o;
}
__global__ void cvt_h0_kernel(const float* __restrict__ h0, int total8) {
    int i = blockIdx.x * blockDim.x + threadIdx.x;
    if (i >= total8) return;
    const float4* p = reinterpret_cast<const float4*>(h0) + (size_t)i * 2;
    float4 a = __ldg(p);
    float4 b = __ldg(p + 1);
    __half2 q0 = __floats2half2_rn(a.x, a.y);
    __half2 q1 = __floats2half2_rn(a.z, a.w);
    __half2 q2 = __floats2half2_rn(b.x, b.y);
    __half2 q3 = __floats2half2_rn(b.z, b.w);
    uint4 o;
    o.x = *reinterpret_cast<uint32_t*>(&q0);
    o.y = *reinterpret_cast<uint32_t*>(&q1);
    o.z = *reinterpret_cast<uint32_t*>(&q2);
    o.w = *reinterpret_cast<uint32_t*>(&q3);
    reinterpret_cast<uint4*>(g_h0h)[i] = o;
}

// Build transposed fp16 blend matrix g_Mth[n][k]
__global__ void build_Mt_kernel(const float* __restrict__ W1,
                                const float* __restrict__ W2,
                                const float* __restrict__ p_alpha,
                                const float* __restrict__ p_beta) {
    float a = *p_alpha, b = *p_beta;
    float c1 = (1.f - a) * (1.f - b);
    float c2 = (1.f - a) * b;
    float c3 = a * (1.f - b);
    float c4 = a * b;
    int i = blockIdx.x * blockDim.x + threadIdx.x;
    if (i >= C * KTOT) return;
    int n = i / KTOT, k = i % KTOT;
    float v;
    if (k < C) {
        v = c2 * W1[k * C + n] + (k == n ? c1 : 0.f);
    } else {
        int k2 = k - C;
        v = c4 * W2[k2 * C + n] + (k2 == n ? c3 : 0.f);
    }
    g_Mth[i] = __float2half_rn(v);
}

// ---------------------------------------------------------------------------
// CSR build: histogram (4-wide) -> 3-phase scan -> ticket scatter
// ---------------------------------------------------------------------------
__global__ void hist_kernel(const void* __restrict__ ei_raw, int E, int N) {
    const int is64 = g_is64;
    const long long* ei64 = (const long long*)ei_raw;
    const int*       ei32 = (const int*)ei_raw;
    int base   = (blockIdx.x * blockDim.x + threadIdx.x) * 4;
    int stride = gridDim.x * blockDim.x * 4;
    for (int e = base; e + 4 <= E; e += stride) {
        int r0, r1, r2, r3;
        if (is64) {
            longlong2 p0 = __ldg(reinterpret_cast<const longlong2*>(&ei64[e]));
            longlong2 p1 = __ldg(reinterpret_cast<const longlong2*>(&ei64[e + 2]));
            r0 = (int)p0.x; r1 = (int)p0.y; r2 = (int)p1.x; r3 = (int)p1.y;
        } else {
            int4 p = __ldg(reinterpret_cast<const int4*>(&ei32[e]));
            r0 = p.x; r1 = p.y; r2 = p.z; r3 = p.w;
        }
        if ((unsigned)r0 < (unsigned)N) atomicAdd(&g_cnt[r0], 1);
        if ((unsigned)r1 < (unsigned)N) atomicAdd(&g_cnt[r1], 1);
        if ((unsigned)r2 < (unsigned)N) atomicAdd(&g_cnt[r2], 1);
        if ((unsigned)r3 < (unsigned)N) atomicAdd(&g_cnt[r3], 1);
    }
    if (base == 0) {
        for (int e = E & ~3; e < E; e++) {
            int r = is64 ? (int)__ldg(&ei64[e]) : __ldg(&ei32[e]);
            if ((unsigned)r < (unsigned)N) atomicAdd(&g_cnt[r], 1);
        }
    }
}

__global__ void scan_p1(int N) {
    int j = blockIdx.x * blockDim.x + threadIdx.x;
    if (j >= NCH) return;
    int ch = (N + NCH - 1) / NCH;
    int s = j * ch, e = min(s + ch, N);
    int acc = 0;
    for (int i = s; i < e; i++) acc += g_cnt[i];
    g_psum[j] = acc;
}

__global__ void scan_p2() {
    __shared__ int sh[1024];
    int t = threadIdx.x;
    int loc[8];
    int s = 0;
    #pragma unroll
    for (int k = 0; k < 8; k++) { loc[k] = g_psum[t * 8 + k]; s += loc[k]; }
    sh[t] = s;
    __syncthreads();
    for (int off = 1; off < 1024; off <<= 1) {
        int add = (t >= off) ? sh[t - off] : 0;
        __syncthreads();
        sh[t] += add;
        __syncthreads();
    }
    int run = sh[t] - s;
    #pragma unroll
    for (int k = 0; k < 8; k++) { g_poff[t * 8 + k] = run; run += loc[k]; }
}

__global__ void scan_p3(int N, int E) {
    int j = blockIdx.x * blockDim.x + threadIdx.x;
    if (j >= NCH) return;
    int ch = (N + NCH - 1) / NCH;
    int s = j * ch, e = min(s + ch, N);
    int base = g_poff[j];
    for (int i = s; i < e; i++) {
        int c = g_cnt[i];
        g_rowstart[i] = base;
        g_cursor[i]   = base;
        base += c;
    }
    if (j == 0) g_rowstart[N] = E;
}

__global__ void scatter_kernel(const void* __restrict__ ei_raw,
                               const float* __restrict__ vals, int E, int N) {
    const int is64 = g_is64;
    const long long* ei64 = (const long long*)ei_raw;
    const int*       ei32 = (const int*)ei_raw;
    for (int e = blockIdx.x * blockDim.x + threadIdx.x; e < E;
         e += gridDim.x * blockDim.x) {
        int row, col;
        if (is64) {
            row = (int)__ldg(&ei64[e]);
            col = (int)__ldg(&ei64[(size_t)E + e]);
        } else {
            row = __ldg(&ei32[e]);
            col = __ldg(&ei32[(size_t)E + e]);
        }
        if ((unsigned)row >= (unsigned)N || (unsigned)col >= (unsigned)N) continue;
        int pos = atomicAdd(&g_cursor[row], 1);
        __stcs(&g_colval[pos],
               make_uint2((unsigned)col, __float_as_uint(__ldg(&vals[e]))));
    }
}

// ---------------------------------------------------------------------------
// SpMM over CSR: one warp per row; fp16 x gathers (16B/lane), 4-edge unroll;
// fp32 accumulate; epilogue stores fp16 ax (one uint4 per lane).
// ---------------------------------------------------------------------------
__device__ __forceinline__ void accum8(float* acc, uint4 a, float v) {
    __half2* h = reinterpret_cast<__half2*>(&a);
    #pragma unroll
    for (int q = 0; q < 4; q++) {
        float2 f = __half22float2(h[q]);
        acc[2 * q]     += v * f.x;
        acc[2 * q + 1] += v * f.y;
    }
}

__global__ __launch_bounds__(256)
void spmm_csr_kernel(int N) {
    int warp = (blockIdx.x * blockDim.x + threadIdx.x) >> 5;
    int lane = threadIdx.x & 31;
    int nw   = (gridDim.x * blockDim.x) >> 5;
    for (int r = warp; r < N; r += nw) {
        int s = g_rowstart[r];
        int e = g_rowstart[r + 1];
        float acc[8];
        #pragma unroll
        for (int q = 0; q < 8; q++) acc[q] = 0.f;
        int i = s;
        for (; i + 4 <= e; i += 4) {
            uint2 cv0 = __ldcs(&g_colval[i]);
            uint2 cv1 = __ldcs(&g_colval[i + 1]);
            uint2 cv2 = __ldcs(&g_colval[i + 2]);
            uint2 cv3 = __ldcs(&g_colval[i + 3]);
            uint4 a0 = __ldg(reinterpret_cast<const uint4*>(
                                 g_xh + (size_t)cv0.x * C) + lane);
            uint4 a1 = __ldg(reinterpret_cast<const uint4*>(
                                 g_xh + (size_t)cv1.x * C) + lane);
            uint4 a2 = __ldg(reinterpret_cast<const uint4*>(
                                 g_xh + (size_t)cv2.x * C) + lane);
            uint4 a3 = __ldg(reinterpret_cast<const uint4*>(
                                 g_xh + (size_t)cv3.x * C) + lane);
            accum8(acc, a0, __uint_as_float(cv0.y));
            accum8(acc, a1, __uint_as_float(cv1.y));
            accum8(acc, a2, __uint_as_float(cv2.y));
            accum8(acc, a3, __uint_as_float(cv3.y));
        }
        for (; i < e; i++) {
            uint2 cv0 = __ldcs(&g_colval[i]);
            uint4 a0 = __ldg(reinterpret_cast<const uint4*>(
                                 g_xh + (size_t)cv0.x * C) + lane);
            accum8(acc, a0, __uint_as_float(cv0.y));
        }
        // fp16 store: lane covers cols [8*lane, 8*lane+8)
        __half2 q0 = __floats2half2_rn(acc[0], acc[1]);
        __half2 q1 = __floats2half2_rn(acc[2], acc[3]);
        __half2 q2 = __floats2half2_rn(acc[4], acc[5]);
        __half2 q3 = __floats2half2_rn(acc[6], acc[7]);
        uint4 o;
        o.x = *reinterpret_cast<uint32_t*>(&q0);
        o.y = *reinterpret_cast<uint32_t*>(&q1);
        o.z = *reinterpret_cast<uint32_t*>(&q2);
        o.w = *reinterpret_cast<uint32_t*>(&q3);
        __stcs(reinterpret_cast<uint4*>(g_axh + (size_t)r * C + lane * 8), o);
    }
}

// ---------------------------------------------------------------------------
// Single-term fp16 tensor-core GEMM: out[N,256] = [ax|h0] @ M (K=512).
// Tile 128x64, BK=32, 8 warps of 32x32, fp32 accumulate.
// ---------------------------------------------------------------------------
#define BM 128
#define BN 64
#define BK 32
#define LDS_W 20                          // words/row: 16 data + 4 pad
#define A_ARR_W (128 * LDS_W)             // 2560 words
#define B_ARR_W (64 * LDS_W)              // 1280 words
#define STG_W (A_ARR_W + B_ARR_W)         // 3840 words = 15360 B
#define SMEM_BYTES (2 * STG_W * 4)        // 30720 B

__device__ __forceinline__ uint32_t s2u(const void* p) {
    uint32_t a;
    asm("{ .reg .u64 t; cvta.to.shared.u64 t, %1; cvt.u32.u64 %0, t; }"
        : "=r"(a) : "l"(p));
    return a;
}
__device__ __forceinline__ void cp16(uint32_t daddr, const void* g) {
    asm volatile("cp.async.cg.shared.global [%0], [%1], 16;"
                 :: "r"(daddr), "l"(g));
}
__device__ __forceinline__ void cp16z(uint32_t daddr, const void* g) {
    asm volatile("cp.async.cg.shared.global [%0], [%1], 16, 0;"
                 :: "r"(daddr), "l"(g));
}
__device__ __forceinline__ void cp_commit() {
    asm volatile("cp.async.commit_group;");
}
__device__ __forceinline__ void cp_wait0() {
    asm volatile("cp.async.wait_group 0;");
}
__device__ __forceinline__ void ldm_x4(uint32_t* r, uint32_t addr) {
    asm volatile("ldmatrix.sync.aligned.m8n8.x4.shared.b16 {%0,%1,%2,%3}, [%4];"
                 : "=r"(r[0]), "=r"(r[1]), "=r"(r[2]), "=r"(r[3]) : "r"(addr));
}
__device__ __forceinline__ void mma_f16(float* c, const uint32_t* a,
                                        uint32_t b0, uint32_t b1) {
    asm volatile(
        "mma.sync.aligned.m16n8k16.row.col.f32.f16.f16.f32 "
        "{%0,%1,%2,%3}, {%4,%5,%6,%7}, {%8,%9}, {%0,%1,%2,%3};"
        : "+f"(c[0]), "+f"(c[1]), "+f"(c[2]), "+f"(c[3])
        : "r"(a[0]), "r"(a[1]), "r"(a[2]), "r"(a[3]), "r"(b0), "r"(b1));
}

__global__ __launch_bounds__(256, 3)
void gemm_f16_kernel(float* __restrict__ out, int N) {
    extern __shared__ uint32_t smem[];
    const uint32_t sbase = s2u(smem);

    const int tid  = threadIdx.x;
    const int lane = tid & 31;
    const int wid  = tid >> 5;
    const int warp_m = (wid & 3) * 32;
    const int warp_n = (wid >> 2) * 32;
    const int bn = blockIdx.x * BN;
    const int bm = blockIdx.y * BM;

    const int a_row = (lane & 7) + ((lane >> 3) & 1) * 8;
    const int a_k   = (lane >> 4) * 8;
    const int b_row = (lane & 7) + (lane >> 4) * 8;
    const int b_k   = ((lane >> 3) & 1) * 8;

    float acc[2][4][4];
    #pragma unroll
    for (int i = 0; i < 2; i++)
        #pragma unroll
        for (int j = 0; j < 4; j++)
            #pragma unroll
            for (int q = 0; q < 4; q++) acc[i][j][q] = 0.f;

    // A loader: 128 rows x 4 chunks(16B) = 512 chunks; 2 per thread
    const int lrow = tid >> 1;
    const int lc   = tid & 1;
    const int arow = bm + lrow;
    const bool avalid = (arow < N);
    const int acl = avalid ? arow : 0;
    // B loader: 64 rows x 4 chunks = 256 chunks; 1 per thread
    const int brow = tid >> 2;
    const int bq   = tid & 3;

    const int T = KTOT / BK;   // 16 tiles

    auto load_tile = [&](int t, int stg) {
        const int kt = t * BK;
        const size_t aoff = (size_t)acl * C + ((kt < C) ? kt : kt - C);
        const __half* gA = (kt < C) ? (g_axh + aoff) : (g_h0h + aoff);
        uint32_t drow = sbase + (stg * STG_W + lrow * LDS_W) * 4;
        #pragma unroll
        for (int c = 0; c < 2; c++) {
            int chunk = lc * 2 + c;
            if (avalid) cp16(drow + chunk * 16, gA + chunk * 8);
            else        cp16z(drow + chunk * 16, gA + chunk * 8);
        }
        const size_t boff = (size_t)(bn + brow) * KTOT + kt + bq * 8;
        uint32_t db = sbase + (stg * STG_W + A_ARR_W + brow * LDS_W) * 4 + bq * 16;
        cp16(db, g_Mth + boff);
        cp_commit();
    };

    load_tile(0, 0);

    for (int t = 0; t < T; t++) {
        cp_wait0();
        __syncthreads();
        if (t + 1 < T) load_tile(t + 1, (t + 1) & 1);

        const int stg = t & 1;
        const uint32_t aS0 = sbase + (stg * STG_W) * 4;
        const uint32_t bS0 = aS0 + A_ARR_W * 4;

        #pragma unroll
        for (int ks = 0; ks < 2; ks++) {
            const int kk = ks * 16;
            uint32_t aR[2][4];
            #pragma unroll
            for (int mt = 0; mt < 2; mt++) {
                uint32_t off = ((warp_m + mt * 16 + a_row) * LDS_W) * 4
                             + (kk + a_k) * 2;
                ldm_x4(aR[mt], aS0 + off);
            }
            #pragma unroll
            for (int ntp = 0; ntp < 2; ntp++) {
                uint32_t bR[4];
                uint32_t off = ((warp_n + ntp * 16 + b_row) * LDS_W) * 4
                             + (kk + b_k) * 2;
                ldm_x4(bR, bS0 + off);
                #pragma unroll
                for (int mt = 0; mt < 2; mt++) {
                    #pragma unroll
                    for (int j = 0; j < 2; j++) {
                        mma_f16(acc[mt][ntp * 2 + j], aR[mt],
                                bR[2 * j], bR[2 * j + 1]);
                    }
                }
            }
        }
        __syncthreads();
    }

    #pragma unroll
    for (int mt = 0; mt < 2; mt++) {
        #pragma unroll
        for (int nt = 0; nt < 4; nt++) {
            int r0  = bm + warp_m + mt * 16 + (lane >> 2);
            int col = bn + warp_n + nt * 8 + (lane & 3) * 2;
            if (r0 < N)
                *reinterpret_cast<float2*>(out + (size_t)r0 * C + col) =
                    make_float2(acc[mt][nt][0], acc[mt][nt][1]);
            int r1 = r0 + 8;
            if (r1 < N)
                *reinterpret_cast<float2*>(out + (size_t)r1 * C + col) =
                    make_float2(acc[mt][nt][2], acc[mt][nt][3]);
        }
    }
}

// ---------------------------------------------------------------------------
// Launch (serial single stream)
// ---------------------------------------------------------------------------
extern "C" void kernel_launch(void* const* d_in, const int* in_sizes, int n_in,
                              void* d_out, int out_size) {
    const float* x    = (const float*)d_in[0];
    const float* vals = (const float*)d_in[1];
    const void*  ei   = d_in[2];
    const float* h0   = (const float*)d_in[3];
    const float* W1   = (const float*)d_in[4];
    const float* W2   = (const float*)d_in[5];
    const float* pa   = (const float*)d_in[6];
    const float* pb   = (const float*)d_in[7];
    float* out = (float*)d_out;

    const int N = in_sizes[0] / C;     // 100000
    int E = in_sizes[1];               // 3200000
    if (E > MAXE) E = MAXE;

    static bool inited = false;
    if (!inited) {
        cudaFuncSetAttribute(gemm_f16_kernel,
                             cudaFuncAttributeMaxDynamicSharedMemorySize,
                             SMEM_BYTES);
        inited = true;
    }

    detect_idx_kernel<<<1, 32>>>((const int*)ei, in_sizes[2]);
    int total8 = N * C / 8;
    cvt_x_kernel<<<(total8 + 255) / 256, 256>>>(x, total8);
    cvt_h0_kernel<<<(total8 + 255) / 256, 256>>>(h0, total8);
    build_Mt_kernel<<<(C * KTOT + 255) / 256, 256>>>(W1, W2, pa, pb);

    zero_cnt_kernel<<<(N + 255) / 256, 256>>>(N);
    hist_kernel<<<3125, 256>>>(ei, E, N);
    scan_p1<<<NCH / 256, 256>>>(N);
    scan_p2<<<1, 1024>>>();
    scan_p3<<<NCH / 256, 256>>>(N, E);
    scatter_kernel<<<4096, 256>>>(ei, vals, E, N);

    int spmm_blocks = (N * 32 + 255) / 256;
    spmm_csr_kernel<<<spmm_blocks, 256>>>(N);

    dim3 grid(C / BN, (N + BM - 1) / BM);   // (4, 782)
    gemm_f16_kernel<<<grid, 256, SMEM_BYTES>>>(out, N);
}